// round 11
// baseline (speedup 1.0000x reference)
#include <cuda_runtime.h>
#include <cuda_bf16.h>
#include <math.h>

#define FULL_MASK 0xFFFFFFFFu

// Scratch: chosen FPS indices and the encoded distance matrix
// (bs*n*n = 4*2048*2048 uint32 = 64 MB; fits in GB300's ~126 MB L2).
__device__ int      g_qidx[8192];
__device__ unsigned g_dm[4L * 2048 * 2048];

// ---------------------------------------------------------------------------
// Mask dtype handling (bool may arrive as u8 / i32 / f32; mask[0] is True).
// ---------------------------------------------------------------------------
__device__ __forceinline__ int mask_mode(const void* mask) {
    unsigned u0 = *(const unsigned*)mask;
    if (u0 == 0x3F800000u) return 2;   // f32
    if (u0 == 1u)          return 1;   // i32
    return 0;                          // byte
}
__device__ __forceinline__ bool mask_at(const void* mask, int mode, long idx) {
    if (mode == 0) return ((const unsigned char*)mask)[idx] != 0;
    if (mode == 1) return ((const int*)mask)[idx] != 0;
    return ((const float*)mask)[idx] != 0.0f;
}

// Monotone (order-preserving) float -> uint32 encoding.
__device__ __forceinline__ unsigned enc_f32(float f) {
    unsigned u = __float_as_uint(f);
    unsigned s = (unsigned)((int)u >> 31);        // all-ones if negative
    return u ^ (s | 0x80000000u);
}

// ---------------------------------------------------------------------------
// Precompute: g_dm[b,i,j] = enc( mask[b,j] ? ||abq[b,i,j,:]|| : -100 ).
// One thread per 8 consecutive j: 8x LDG.128 (128B in, MLP=8) and
// 2x STG.128 (32B out), fully coalesced (warp = 4KB contiguous read).
// Default cache policy (__ldg) — R9 proved __ldcs costs ~65us in fps.
// ---------------------------------------------------------------------------
__global__ void precompute_kernel(const float4* __restrict__ abq,
                                  const void* __restrict__ mask,
                                  int n, int total8) {
    int idx = blockIdx.x * blockDim.x + threadIdx.x;
    if (idx >= total8) return;
    const int n8 = n >> 3;
    int j8 = idx % n8;
    int r  = idx / n8;
    int b  = r / n;

    const int  mode = mask_mode(mask);
    const long mb   = (long)b * n + (long)j8 * 8;

    const float4* src = abq + (size_t)idx * 8;
    float4 a[8];
    #pragma unroll
    for (int k = 0; k < 8; k++) a[k] = __ldg(src + k);

    unsigned out[8];
    #pragma unroll
    for (int k = 0; k < 8; k++) {
        float nrm = sqrtf(a[k].x*a[k].x + a[k].y*a[k].y
                        + a[k].z*a[k].z + a[k].w*a[k].w);
        bool mk = mask_at(mask, mode, mb + k);
        out[k] = enc_f32(mk ? nrm : -100.0f);
    }
    uint4* dst = (uint4*)g_dm + (size_t)idx * 2;
    dst[0] = make_uint4(out[0], out[1], out[2], out[3]);
    dst[1] = make_uint4(out[4], out[5], out[6], out[7]);
}

// ---------------------------------------------------------------------------
// FPS: one block per batch, 512 threads, 4 j's per thread (blocked layout so
// lane order == j order for first-occurrence tie-breaks).
// Per iter: 1 uint4 L2 load, 4 umin, local argmax, REDUX warp argmax,
// ONE barrier, redundant per-warp final reduce (double-buffered smem slots).
// (FROZEN: exact R2/R6 version — seven modification attempts all regressed.)
// ---------------------------------------------------------------------------
__global__ void __launch_bounds__(512, 1)
fps_kernel(const void* __restrict__ mask, const int* __restrict__ rand_start,
           int n, int m) {
    const int b    = blockIdx.x;
    const int tid  = threadIdx.x;
    const int nthr = blockDim.x;            // 512
    const int lane = tid & 31;
    const int warp = tid >> 5;               // 0..15

    extern __shared__ unsigned char smem[];
    unsigned char* s_mask = smem;                         // n bytes
    unsigned* s_key = (unsigned*)(smem + ((n + 7) & ~7)); // [2][16]
    int*      s_idx = (int*)(s_key + 32);                 // [2][16]
    int*      s_far = s_idx + 32;

    // Stage mask (needed only for the initial k-th-valid index).
    const int  mode  = mask_mode(mask);
    const long mbase = (long)b * n;
    for (int j = tid; j < n; j += nthr)
        s_mask[j] = mask_at(mask, mode, mbase + j) ? 1 : 0;
    __syncthreads();

    // Initial farthest = index of k-th True, k = rand_start[b] % count.
    if (tid < 32) {
        const int chunk = (n + 31) / 32;
        const int base  = lane * chunk;
        int cnt = 0;
        for (int i = 0; i < chunk; i++) {
            int jj = base + i;
            if (jj < n) cnt += s_mask[jj];
        }
        int inc = cnt;
        #pragma unroll
        for (int off = 1; off < 32; off <<= 1) {
            int v = __shfl_up_sync(FULL_MASK, inc, off);
            if (lane >= off) inc += v;
        }
        const int total = __shfl_sync(FULL_MASK, inc, 31);
        const int k     = rand_start[b] % total;
        const int excl  = inc - cnt;
        if (k >= excl && k < inc) {
            int need = k - excl;
            for (int i = 0; i < chunk; i++) {
                int jj = base + i;
                if (jj < n && s_mask[jj]) {
                    if (need == 0) { *s_far = jj; break; }
                    need--;
                }
            }
        }
    }
    __syncthreads();
    int far = *s_far;

    // Encoded running distances (init enc(1e8)).
    const unsigned E_INIT = enc_f32(1e8f);
    uint4 dist = make_uint4(E_INIT, E_INIT, E_INIT, E_INIT);

    const uint4* dmb = (const uint4*)(g_dm) + (size_t)b * n * (n >> 2);

    for (int t = 0; t < m; t++) {
        if (tid == 0) g_qidx[b * m + t] = far;

        // Row read: 8 KB from L2 (whole dm fits in L2 after precompute).
        uint4 v = __ldg(dmb + (size_t)far * (n >> 2) + tid);
        dist.x = min(dist.x, v.x);
        dist.y = min(dist.y, v.y);
        dist.z = min(dist.z, v.z);
        dist.w = min(dist.w, v.w);

        // Local argmax over 4 (tie -> lowest j).
        unsigned bk = dist.x; int bj = 0;
        if (dist.y > bk) { bk = dist.y; bj = 1; }
        if (dist.z > bk) { bk = dist.z; bj = 2; }
        if (dist.w > bk) { bk = dist.w; bj = 3; }
        bj += tid << 2;

        // Warp argmax via REDUX; tie -> lowest lane == lowest j (blocked).
        unsigned mk   = __reduce_max_sync(FULL_MASK, bk);
        unsigned ball = __ballot_sync(FULL_MASK, bk == mk);
        int src       = __ffs(ball) - 1;
        int wj        = __shfl_sync(FULL_MASK, bj, src);
        const int buf = t & 1;
        if (lane == 0) { s_key[buf * 16 + warp] = mk; s_idx[buf * 16 + warp] = wj; }
        __syncthreads();

        // Redundant final reduce in EVERY warp (no second barrier needed:
        // next iter writes the other buffer, and its own barrier fences it).
        unsigned k2 = 0; int j2 = 0;
        if (lane < 16) { k2 = s_key[buf * 16 + lane]; j2 = s_idx[buf * 16 + lane]; }
        unsigned mk2   = __reduce_max_sync(FULL_MASK, k2);
        unsigned ball2 = __ballot_sync(FULL_MASK, k2 == mk2);
        int src2       = __ffs(ball2) - 1;
        far            = __shfl_sync(FULL_MASK, j2, src2);
    }
}

// ---------------------------------------------------------------------------
// Merged gathers: pairs (sub_abq float4 + sub_edges float2) then small
// (sub_vals float4 chunks + sub_mask) in one launch.
// ---------------------------------------------------------------------------
__global__ void gather_kernel(const float4* __restrict__ abq,
                              const float2* __restrict__ edges,
                              const float4* __restrict__ vals4,
                              const void* __restrict__ mask,
                              float4* __restrict__ out_abq,
                              float2* __restrict__ out_edges,
                              float4* __restrict__ out_vals,
                              float* __restrict__ out_mask,
                              int n, int m, int bs, int c4) {
    int idx = blockIdx.x * blockDim.x + threadIdx.x;
    int total_pairs = bs * m * m;
    if (idx < total_pairs) {
        int j = idx % m;
        int r = idx / m;
        int i = r % m;
        int b = r / m;
        int qi = g_qidx[b * m + i];
        int qj = g_qidx[b * m + j];
        size_t src = ((size_t)b * n + (size_t)qi) * (size_t)n + (size_t)qj;
        out_abq[idx]   = __ldg(abq + src);
        out_edges[idx] = __ldg(edges + src);
    } else {
        int k = idx - total_pairs;
        if (k >= bs * m * c4) return;
        int ch = k % c4;
        int r  = k / c4;
        int i  = r % m;
        int b  = r / m;
        int qi = g_qidx[b * m + i];
        out_vals[k] = __ldg(vals4 + ((size_t)b * n + (size_t)qi) * (size_t)c4 + ch);
        if (ch == 0) {
            int mode = mask_mode(mask);
            out_mask[b * m + i] = mask_at(mask, mode, (long)b * n + qi) ? 1.0f : 0.0f;
        }
    }
}

// ---------------------------------------------------------------------------
// Launch. Inputs: abq_pairs f32 (bs,n,n,4), vals f32 (bs,n,64), mask bool
// (bs,n), edges f32 (bs,n,n,2), rand_start i32 (bs).
// Output: [sub_abq | sub_vals | sub_mask | sub_edges] as f32.
// ---------------------------------------------------------------------------
extern "C" void kernel_launch(void* const* d_in, const int* in_sizes, int n_in,
                              void* d_out, int out_size) {
    const float4* abq   = (const float4*)d_in[0];
    const float4* vals4 = (const float4*)d_in[1];
    const void*   mask  = (const void*)d_in[2];
    const float2* edges = (const float2*)d_in[3];
    const int*    rnd   = (const int*)d_in[4];

    const int bs = in_sizes[4];                 // 4
    const int n  = in_sizes[2] / bs;            // 2048
    const int m  = n / 4;                       // 512
    const int c  = in_sizes[1] / (bs * n);      // 64
    const int c4 = c / 4;

    float* out = (float*)d_out;
    float4* out_abq    = (float4*)out;
    float*  out_vals_f = out + (size_t)bs * m * m * 4;
    float*  out_mask   = out_vals_f + (size_t)bs * m * c;
    float2* out_edges  = (float2*)(out_mask + (size_t)bs * m);

    // 1) Precompute encoded masked-distance matrix (8-wide tiles, MLP=8).
    int total8 = bs * n * (n / 8);
    precompute_kernel<<<(total8 + 255) / 256, 256>>>(abq, mask, n, total8);

    // 2) Sequential FPS on the L2-resident encoded matrix (frozen R6 loop).
    size_t smem = (size_t)((n + 7) & ~7) + 32 * sizeof(unsigned)
                + 32 * sizeof(int) + sizeof(int);
    fps_kernel<<<bs, 512, smem>>>(mask, rnd, n, m);

    // 3) Merged output gathers.
    int total = bs * m * m + bs * m * c4;
    gather_kernel<<<(total + 255) / 256, 256>>>(
        abq, edges, vals4, mask,
        out_abq, out_edges, (float4*)out_vals_f, out_mask, n, m, bs, c4);
}

// round 12
// speedup vs baseline: 2.0772x; 2.0772x over previous
#include <cuda_runtime.h>
#include <cuda_bf16.h>
#include <math.h>

#define FULL_MASK 0xFFFFFFFFu

// Scratch: chosen FPS indices and the encoded distance matrix
// (bs*n*n = 4*2048*2048 uint32 = 64 MB; fits in GB300's ~126 MB L2).
__device__ int      g_qidx[8192];
__device__ unsigned g_dm[4L * 2048 * 2048];

// ---------------------------------------------------------------------------
// Mask dtype handling (bool may arrive as u8 / i32 / f32; mask[0] is True).
// ---------------------------------------------------------------------------
__device__ __forceinline__ int mask_mode(const void* mask) {
    unsigned u0 = *(const unsigned*)mask;
    if (u0 == 0x3F800000u) return 2;   // f32
    if (u0 == 1u)          return 1;   // i32
    return 0;                          // byte
}
__device__ __forceinline__ bool mask_at(const void* mask, int mode, long idx) {
    if (mode == 0) return ((const unsigned char*)mask)[idx] != 0;
    if (mode == 1) return ((const int*)mask)[idx] != 0;
    return ((const float*)mask)[idx] != 0.0f;
}

// Monotone (order-preserving) float -> uint32 encoding.
__device__ __forceinline__ unsigned enc_f32(float f) {
    unsigned u = __float_as_uint(f);
    unsigned s = (unsigned)((int)u >> 31);        // all-ones if negative
    return u ^ (s | 0x80000000u);
}

// ---------------------------------------------------------------------------
// Precompute: g_dm[b,i,j] = enc( mask[b,j] ? ||abq[b,i,j,:]|| : -100 ).
// One thread per 4 consecutive j (64B load / 16B store, fully coalesced).
// EXACT R6 version — measured 52us at 77% DRAM; 8-wide (R11) and __ldcs (R9)
// both regressed.
// ---------------------------------------------------------------------------
__global__ void precompute_kernel(const float4* __restrict__ abq,
                                  const void* __restrict__ mask,
                                  int n, int total4) {
    int idx = blockIdx.x * blockDim.x + threadIdx.x;
    if (idx >= total4) return;
    const int nq = n >> 2;
    int j4 = idx % nq;
    int r  = idx / nq;
    int b  = r / n;

    const int mode = mask_mode(mask);
    const float4* src = abq + (size_t)idx * 4;
    unsigned out[4];
    #pragma unroll
    for (int k = 0; k < 4; k++) {
        float4 v = __ldg(src + k);
        float nrm = sqrtf(v.x*v.x + v.y*v.y + v.z*v.z + v.w*v.w);
        bool mk = mask_at(mask, mode, (long)b * n + j4 * 4 + k);
        out[k] = enc_f32(mk ? nrm : -100.0f);
    }
    ((uint4*)g_dm)[idx] = make_uint4(out[0], out[1], out[2], out[3]);
}

// ---------------------------------------------------------------------------
// FPS: one block per batch, 512 threads, 4 j's per thread (blocked layout so
// lane order == j order for first-occurrence tie-breaks).
// R6 structure (1 uint4 L2 load, local argmax, warp reduce, ONE barrier,
// redundant per-warp final reduce on double-buffered slots) with ONE change:
// winner-index broadcast uses select + __reduce_min_sync instead of
// ballot+ffs+shfl (same exact semantics: ties -> min index; ~25 cyc cheaper
// per stage, two stages per iteration).
// ---------------------------------------------------------------------------
__global__ void __launch_bounds__(512, 1)
fps_kernel(const void* __restrict__ mask, const int* __restrict__ rand_start,
           int n, int m) {
    const int b    = blockIdx.x;
    const int tid  = threadIdx.x;
    const int nthr = blockDim.x;            // 512
    const int lane = tid & 31;
    const int warp = tid >> 5;               // 0..15

    extern __shared__ unsigned char smem[];
    unsigned char* s_mask = smem;                         // n bytes
    unsigned* s_key = (unsigned*)(smem + ((n + 7) & ~7)); // [2][16]
    int*      s_idx = (int*)(s_key + 32);                 // [2][16]
    int*      s_far = s_idx + 32;

    // Stage mask (needed only for the initial k-th-valid index).
    const int  mode  = mask_mode(mask);
    const long mbase = (long)b * n;
    for (int j = tid; j < n; j += nthr)
        s_mask[j] = mask_at(mask, mode, mbase + j) ? 1 : 0;
    __syncthreads();

    // Initial farthest = index of k-th True, k = rand_start[b] % count.
    if (tid < 32) {
        const int chunk = (n + 31) / 32;
        const int base  = lane * chunk;
        int cnt = 0;
        for (int i = 0; i < chunk; i++) {
            int jj = base + i;
            if (jj < n) cnt += s_mask[jj];
        }
        int inc = cnt;
        #pragma unroll
        for (int off = 1; off < 32; off <<= 1) {
            int v = __shfl_up_sync(FULL_MASK, inc, off);
            if (lane >= off) inc += v;
        }
        const int total = __shfl_sync(FULL_MASK, inc, 31);
        const int k     = rand_start[b] % total;
        const int excl  = inc - cnt;
        if (k >= excl && k < inc) {
            int need = k - excl;
            for (int i = 0; i < chunk; i++) {
                int jj = base + i;
                if (jj < n && s_mask[jj]) {
                    if (need == 0) { *s_far = jj; break; }
                    need--;
                }
            }
        }
    }
    __syncthreads();
    int far = *s_far;

    // Encoded running distances (init enc(1e8)).
    const unsigned E_INIT = enc_f32(1e8f);
    uint4 dist = make_uint4(E_INIT, E_INIT, E_INIT, E_INIT);

    const uint4* dmb = (const uint4*)(g_dm) + (size_t)b * n * (n >> 2);

    for (int t = 0; t < m; t++) {
        if (tid == 0) g_qidx[b * m + t] = far;

        // Row read: 8 KB from L2 (whole dm fits in L2 after precompute).
        uint4 v = __ldg(dmb + (size_t)far * (n >> 2) + tid);
        dist.x = min(dist.x, v.x);
        dist.y = min(dist.y, v.y);
        dist.z = min(dist.z, v.z);
        dist.w = min(dist.w, v.w);

        // Local argmax over 4 (tie -> lowest j).
        unsigned bk = dist.x; int bj = 0;
        if (dist.y > bk) { bk = dist.y; bj = 1; }
        if (dist.z > bk) { bk = dist.z; bj = 2; }
        if (dist.w > bk) { bk = dist.w; bj = 3; }
        bj += tid << 2;

        // Warp argmax: REDUX max on keys, then REDUX min on the selected
        // index (ties -> lowest j; exact first-occurrence semantics).
        unsigned mk = __reduce_max_sync(FULL_MASK, bk);
        int      wj = __reduce_min_sync(FULL_MASK,
                                        (bk == mk) ? bj : 0x7FFFFFFF);
        const int buf = t & 1;
        if (lane == 0) { s_key[buf * 16 + warp] = mk; s_idx[buf * 16 + warp] = wj; }
        __syncthreads();

        // Redundant final reduce in EVERY warp (no second barrier needed:
        // next iter writes the other buffer, and its own barrier fences it).
        unsigned k2 = 0; int j2 = 0x7FFFFFFF;
        if (lane < 16) { k2 = s_key[buf * 16 + lane]; j2 = s_idx[buf * 16 + lane]; }
        unsigned mk2 = __reduce_max_sync(FULL_MASK, k2);
        far          = __reduce_min_sync(FULL_MASK,
                                         (k2 == mk2) ? j2 : 0x7FFFFFFF);
    }
}

// ---------------------------------------------------------------------------
// Merged gathers: pairs (sub_abq float4 + sub_edges float2) then small
// (sub_vals float4 chunks + sub_mask) in one launch.
// ---------------------------------------------------------------------------
__global__ void gather_kernel(const float4* __restrict__ abq,
                              const float2* __restrict__ edges,
                              const float4* __restrict__ vals4,
                              const void* __restrict__ mask,
                              float4* __restrict__ out_abq,
                              float2* __restrict__ out_edges,
                              float4* __restrict__ out_vals,
                              float* __restrict__ out_mask,
                              int n, int m, int bs, int c4) {
    int idx = blockIdx.x * blockDim.x + threadIdx.x;
    int total_pairs = bs * m * m;
    if (idx < total_pairs) {
        int j = idx % m;
        int r = idx / m;
        int i = r % m;
        int b = r / m;
        int qi = g_qidx[b * m + i];
        int qj = g_qidx[b * m + j];
        size_t src = ((size_t)b * n + (size_t)qi) * (size_t)n + (size_t)qj;
        out_abq[idx]   = __ldg(abq + src);
        out_edges[idx] = __ldg(edges + src);
    } else {
        int k = idx - total_pairs;
        if (k >= bs * m * c4) return;
        int ch = k % c4;
        int r  = k / c4;
        int i  = r % m;
        int b  = r / m;
        int qi = g_qidx[b * m + i];
        out_vals[k] = __ldg(vals4 + ((size_t)b * n + (size_t)qi) * (size_t)c4 + ch);
        if (ch == 0) {
            int mode = mask_mode(mask);
            out_mask[b * m + i] = mask_at(mask, mode, (long)b * n + qi) ? 1.0f : 0.0f;
        }
    }
}

// ---------------------------------------------------------------------------
// Launch. Inputs: abq_pairs f32 (bs,n,n,4), vals f32 (bs,n,64), mask bool
// (bs,n), edges f32 (bs,n,n,2), rand_start i32 (bs).
// Output: [sub_abq | sub_vals | sub_mask | sub_edges] as f32.
// ---------------------------------------------------------------------------
extern "C" void kernel_launch(void* const* d_in, const int* in_sizes, int n_in,
                              void* d_out, int out_size) {
    const float4* abq   = (const float4*)d_in[0];
    const float4* vals4 = (const float4*)d_in[1];
    const void*   mask  = (const void*)d_in[2];
    const float2* edges = (const float2*)d_in[3];
    const int*    rnd   = (const int*)d_in[4];

    const int bs = in_sizes[4];                 // 4
    const int n  = in_sizes[2] / bs;            // 2048
    const int m  = n / 4;                       // 512
    const int c  = in_sizes[1] / (bs * n);      // 64
    const int c4 = c / 4;

    float* out = (float*)d_out;
    float4* out_abq    = (float4*)out;
    float*  out_vals_f = out + (size_t)bs * m * m * 4;
    float*  out_mask   = out_vals_f + (size_t)bs * m * c;
    float2* out_edges  = (float2*)(out_mask + (size_t)bs * m);

    // 1) Precompute encoded masked-distance matrix (R6-exact, ~52us).
    int total4 = bs * n * (n / 4);
    precompute_kernel<<<(total4 + 255) / 256, 256>>>(abq, mask, n, total4);

    // 2) Sequential FPS on the L2-resident encoded matrix.
    size_t smem = (size_t)((n + 7) & ~7) + 32 * sizeof(unsigned)
                + 32 * sizeof(int) + sizeof(int);
    fps_kernel<<<bs, 512, smem>>>(mask, rnd, n, m);

    // 3) Merged output gathers.
    int total = bs * m * m + bs * m * c4;
    gather_kernel<<<(total + 255) / 256, 256>>>(
        abq, edges, vals4, mask,
        out_abq, out_edges, (float4*)out_vals_f, out_mask, n, m, bs, c4);
}

// round 13
// speedup vs baseline: 2.1220x; 1.0216x over previous
#include <cuda_runtime.h>
#include <cuda_bf16.h>
#include <math.h>

#define FULL_MASK 0xFFFFFFFFu

// Scratch: chosen FPS indices and the encoded distance matrix
// (bs*n*n = 4*2048*2048 uint32 = 64 MB; fits in GB300's ~126 MB L2).
__device__ int      g_qidx[8192];
__device__ unsigned g_dm[4L * 2048 * 2048];

// ---------------------------------------------------------------------------
// Mask dtype handling (bool may arrive as u8 / i32 / f32; mask[0] is True).
// ---------------------------------------------------------------------------
__device__ __forceinline__ int mask_mode(const void* mask) {
    unsigned u0 = *(const unsigned*)mask;
    if (u0 == 0x3F800000u) return 2;   // f32
    if (u0 == 1u)          return 1;   // i32
    return 0;                          // byte
}
__device__ __forceinline__ bool mask_at(const void* mask, int mode, long idx) {
    if (mode == 0) return ((const unsigned char*)mask)[idx] != 0;
    if (mode == 1) return ((const int*)mask)[idx] != 0;
    return ((const float*)mask)[idx] != 0.0f;
}

// Monotone (order-preserving) float -> uint32 encoding.
__device__ __forceinline__ unsigned enc_f32(float f) {
    unsigned u = __float_as_uint(f);
    unsigned s = (unsigned)((int)u >> 31);        // all-ones if negative
    return u ^ (s | 0x80000000u);
}

// ---------------------------------------------------------------------------
// Precompute: g_dm[b,i,j] = enc( mask[b,j] ? ||abq[b,i,j,:]|| : -100 ).
// One thread per 4 consecutive j (64B load / 16B store, fully coalesced).
// EXACT R6 version — 52us at 77% DRAM; 8-wide (R11) and __ldcs (R9) regressed.
// ---------------------------------------------------------------------------
__global__ void precompute_kernel(const float4* __restrict__ abq,
                                  const void* __restrict__ mask,
                                  int n, int total4) {
    int idx = blockIdx.x * blockDim.x + threadIdx.x;
    if (idx >= total4) return;
    const int nq = n >> 2;
    int j4 = idx % nq;
    int r  = idx / nq;
    int b  = r / n;

    const int mode = mask_mode(mask);
    const float4* src = abq + (size_t)idx * 4;
    unsigned out[4];
    #pragma unroll
    for (int k = 0; k < 4; k++) {
        float4 v = __ldg(src + k);
        float nrm = sqrtf(v.x*v.x + v.y*v.y + v.z*v.z + v.w*v.w);
        bool mk = mask_at(mask, mode, (long)b * n + j4 * 4 + k);
        out[k] = enc_f32(mk ? nrm : -100.0f);
    }
    ((uint4*)g_dm)[idx] = make_uint4(out[0], out[1], out[2], out[3]);
}

// ---------------------------------------------------------------------------
// FPS: one block per batch, 512 threads, 4 j's per thread (blocked layout so
// lane order == j order for first-occurrence tie-breaks).
// R12 structure (REDUX max + select + REDUX min broadcasts, ONE barrier,
// redundant per-warp final reduce on double-buffered slots) with two trims:
//  - per-warp slot packed to u64 (one STS.64 / one LDS.64 instead of 2+2)
//  - tree-shaped local argmax (dep depth 2)
// ---------------------------------------------------------------------------
__global__ void __launch_bounds__(512, 1)
fps_kernel(const void* __restrict__ mask, const int* __restrict__ rand_start,
           int n, int m) {
    const int b    = blockIdx.x;
    const int tid  = threadIdx.x;
    const int nthr = blockDim.x;            // 512
    const int lane = tid & 31;
    const int warp = tid >> 5;               // 0..15

    extern __shared__ unsigned char smem[];
    unsigned char* s_mask = smem;                         // n bytes
    unsigned long long* s_slot =
        (unsigned long long*)(smem + ((n + 7) & ~7));     // [2][16] packed
    int* s_far = (int*)(s_slot + 32);

    // Stage mask (needed only for the initial k-th-valid index).
    const int  mode  = mask_mode(mask);
    const long mbase = (long)b * n;
    for (int j = tid; j < n; j += nthr)
        s_mask[j] = mask_at(mask, mode, mbase + j) ? 1 : 0;
    __syncthreads();

    // Initial farthest = index of k-th True, k = rand_start[b] % count.
    if (tid < 32) {
        const int chunk = (n + 31) / 32;
        const int base  = lane * chunk;
        int cnt = 0;
        for (int i = 0; i < chunk; i++) {
            int jj = base + i;
            if (jj < n) cnt += s_mask[jj];
        }
        int inc = cnt;
        #pragma unroll
        for (int off = 1; off < 32; off <<= 1) {
            int v = __shfl_up_sync(FULL_MASK, inc, off);
            if (lane >= off) inc += v;
        }
        const int total = __shfl_sync(FULL_MASK, inc, 31);
        const int k     = rand_start[b] % total;
        const int excl  = inc - cnt;
        if (k >= excl && k < inc) {
            int need = k - excl;
            for (int i = 0; i < chunk; i++) {
                int jj = base + i;
                if (jj < n && s_mask[jj]) {
                    if (need == 0) { *s_far = jj; break; }
                    need--;
                }
            }
        }
    }
    __syncthreads();
    int far = *s_far;

    // Encoded running distances (init enc(1e8)).
    const unsigned E_INIT = enc_f32(1e8f);
    uint4 dist = make_uint4(E_INIT, E_INIT, E_INIT, E_INIT);

    const uint4* dmb = (const uint4*)(g_dm) + (size_t)b * n * (n >> 2);

    for (int t = 0; t < m; t++) {
        if (tid == 0) g_qidx[b * m + t] = far;

        // Row read: 8 KB from L2 (whole dm fits in L2 after precompute).
        uint4 v = __ldg(dmb + (size_t)far * (n >> 2) + tid);
        dist.x = min(dist.x, v.x);
        dist.y = min(dist.y, v.y);
        dist.z = min(dist.z, v.z);
        dist.w = min(dist.w, v.w);

        // Local argmax over 4, tree-shaped (tie -> lowest j).
        unsigned kxy = (dist.y > dist.x) ? dist.y : dist.x;
        int      jxy = (dist.y > dist.x) ? 1 : 0;
        unsigned kzw = (dist.w > dist.z) ? dist.w : dist.z;
        int      jzw = (dist.w > dist.z) ? 3 : 2;
        unsigned bk  = (kzw > kxy) ? kzw : kxy;
        int      bj  = ((kzw > kxy) ? jzw : jxy) + (tid << 2);

        // Warp argmax: REDUX max on keys, REDUX min on selected index
        // (ties -> lowest j; exact first-occurrence semantics).
        unsigned mk = __reduce_max_sync(FULL_MASK, bk);
        int      wj = __reduce_min_sync(FULL_MASK,
                                        (bk == mk) ? bj : 0x7FFFFFFF);
        const int buf = (t & 1) << 4;
        if (lane == 0)
            s_slot[buf + warp] = ((unsigned long long)mk << 32) | (unsigned)wj;
        __syncthreads();

        // Redundant final reduce in EVERY warp (no second barrier needed:
        // next iter writes the other buffer, and its own barrier fences it).
        unsigned long long pk = (lane < 16) ? s_slot[buf + lane] : 0ull;
        unsigned k2 = (unsigned)(pk >> 32);              // 0 for lanes >= 16
        int      j2 = (int)(unsigned)pk;
        unsigned mk2 = __reduce_max_sync(FULL_MASK, k2); // keys never 0
        far          = __reduce_min_sync(FULL_MASK,
                                         (k2 == mk2) ? j2 : 0x7FFFFFFF);
    }
}

// ---------------------------------------------------------------------------
// Merged gathers: pairs (sub_abq float4 + sub_edges float2) then small
// (sub_vals float4 chunks + sub_mask) in one launch.
// ---------------------------------------------------------------------------
__global__ void gather_kernel(const float4* __restrict__ abq,
                              const float2* __restrict__ edges,
                              const float4* __restrict__ vals4,
                              const void* __restrict__ mask,
                              float4* __restrict__ out_abq,
                              float2* __restrict__ out_edges,
                              float4* __restrict__ out_vals,
                              float* __restrict__ out_mask,
                              int n, int m, int bs, int c4) {
    int idx = blockIdx.x * blockDim.x + threadIdx.x;
    int total_pairs = bs * m * m;
    if (idx < total_pairs) {
        int j = idx % m;
        int r = idx / m;
        int i = r % m;
        int b = r / m;
        int qi = g_qidx[b * m + i];
        int qj = g_qidx[b * m + j];
        size_t src = ((size_t)b * n + (size_t)qi) * (size_t)n + (size_t)qj;
        out_abq[idx]   = __ldg(abq + src);
        out_edges[idx] = __ldg(edges + src);
    } else {
        int k = idx - total_pairs;
        if (k >= bs * m * c4) return;
        int ch = k % c4;
        int r  = k / c4;
        int i  = r % m;
        int b  = r / m;
        int qi = g_qidx[b * m + i];
        out_vals[k] = __ldg(vals4 + ((size_t)b * n + (size_t)qi) * (size_t)c4 + ch);
        if (ch == 0) {
            int mode = mask_mode(mask);
            out_mask[b * m + i] = mask_at(mask, mode, (long)b * n + qi) ? 1.0f : 0.0f;
        }
    }
}

// ---------------------------------------------------------------------------
// Launch. Inputs: abq_pairs f32 (bs,n,n,4), vals f32 (bs,n,64), mask bool
// (bs,n), edges f32 (bs,n,n,2), rand_start i32 (bs).
// Output: [sub_abq | sub_vals | sub_mask | sub_edges] as f32.
// ---------------------------------------------------------------------------
extern "C" void kernel_launch(void* const* d_in, const int* in_sizes, int n_in,
                              void* d_out, int out_size) {
    const float4* abq   = (const float4*)d_in[0];
    const float4* vals4 = (const float4*)d_in[1];
    const void*   mask  = (const void*)d_in[2];
    const float2* edges = (const float2*)d_in[3];
    const int*    rnd   = (const int*)d_in[4];

    const int bs = in_sizes[4];                 // 4
    const int n  = in_sizes[2] / bs;            // 2048
    const int m  = n / 4;                       // 512
    const int c  = in_sizes[1] / (bs * n);      // 64
    const int c4 = c / 4;

    float* out = (float*)d_out;
    float4* out_abq    = (float4*)out;
    float*  out_vals_f = out + (size_t)bs * m * m * 4;
    float*  out_mask   = out_vals_f + (size_t)bs * m * c;
    float2* out_edges  = (float2*)(out_mask + (size_t)bs * m);

    // 1) Precompute encoded masked-distance matrix (R6-exact, ~52us).
    int total4 = bs * n * (n / 4);
    precompute_kernel<<<(total4 + 255) / 256, 256>>>(abq, mask, n, total4);

    // 2) Sequential FPS on the L2-resident encoded matrix.
    size_t smem = (size_t)((n + 7) & ~7) + 32 * sizeof(unsigned long long)
                + sizeof(int);
    fps_kernel<<<bs, 512, smem>>>(mask, rnd, n, m);

    // 3) Merged output gathers.
    int total = bs * m * m + bs * m * c4;
    gather_kernel<<<(total + 255) / 256, 256>>>(
        abq, edges, vals4, mask,
        out_abq, out_edges, (float4*)out_vals_f, out_mask, n, m, bs, c4);
}

// round 14
// speedup vs baseline: 2.2200x; 1.0462x over previous
#include <cuda_runtime.h>
#include <cuda_bf16.h>
#include <math.h>

#define FULL_MASK 0xFFFFFFFFu

// Scratch: chosen FPS indices and the encoded distance matrix
// (bs*n*n = 4*2048*2048 uint32 = 64 MB; fits in GB300's ~126 MB L2).
__device__ int      g_qidx[8192];
__device__ unsigned g_dm[4L * 2048 * 2048];

// ---------------------------------------------------------------------------
// Mask dtype handling (bool may arrive as u8 / i32 / f32; mask[0] is True).
// ---------------------------------------------------------------------------
__device__ __forceinline__ int mask_mode(const void* mask) {
    unsigned u0 = *(const unsigned*)mask;
    if (u0 == 0x3F800000u) return 2;   // f32
    if (u0 == 1u)          return 1;   // i32
    return 0;                          // byte
}
__device__ __forceinline__ bool mask_at(const void* mask, int mode, long idx) {
    if (mode == 0) return ((const unsigned char*)mask)[idx] != 0;
    if (mode == 1) return ((const int*)mask)[idx] != 0;
    return ((const float*)mask)[idx] != 0.0f;
}

// Monotone (order-preserving) float -> uint32 encoding.
__device__ __forceinline__ unsigned enc_f32(float f) {
    unsigned u = __float_as_uint(f);
    unsigned s = (unsigned)((int)u >> 31);        // all-ones if negative
    return u ^ (s | 0x80000000u);
}

// ---------------------------------------------------------------------------
// Precompute: g_dm[b,i,j] = enc( mask[b,j] ? ||abq[b,i,j,:]|| : -100 ).
// One thread per 4 consecutive j (64B load / 16B store, fully coalesced).
// EXACT R6 version — 52us at 77% DRAM; 8-wide (R11) and __ldcs (R9) regressed.
// ---------------------------------------------------------------------------
__global__ void precompute_kernel(const float4* __restrict__ abq,
                                  const void* __restrict__ mask,
                                  int n, int total4) {
    int idx = blockIdx.x * blockDim.x + threadIdx.x;
    if (idx >= total4) return;
    const int nq = n >> 2;
    int j4 = idx % nq;
    int r  = idx / nq;
    int b  = r / n;

    const int mode = mask_mode(mask);
    const float4* src = abq + (size_t)idx * 4;
    unsigned out[4];
    #pragma unroll
    for (int k = 0; k < 4; k++) {
        float4 v = __ldg(src + k);
        float nrm = sqrtf(v.x*v.x + v.y*v.y + v.z*v.z + v.w*v.w);
        bool mk = mask_at(mask, mode, (long)b * n + j4 * 4 + k);
        out[k] = enc_f32(mk ? nrm : -100.0f);
    }
    ((uint4*)g_dm)[idx] = make_uint4(out[0], out[1], out[2], out[3]);
}

// ---------------------------------------------------------------------------
// FPS: one block per batch, 512 threads, 4 j's per thread (blocked layout so
// lane order == j order for first-occurrence tie-breaks).
// R13 structure, two trims:
//  - chosen indices buffered in SMEM (STS) and bulk-written after the loop:
//    keeps the per-iteration STG out of the L1tex global queue ahead of the
//    critical row LDG.
//  - slots carry element offsets (j*nq, i.e. j<<9 for n=2048) so the final
//    REDUX min result feeds the LDG address directly (REDUX min over
//    positive scaled values is order-identical).
// ---------------------------------------------------------------------------
__global__ void __launch_bounds__(512, 1)
fps_kernel(const void* __restrict__ mask, const int* __restrict__ rand_start,
           int n, int m) {
    const int b    = blockIdx.x;
    const int tid  = threadIdx.x;
    const int nthr = blockDim.x;            // 512
    const int lane = tid & 31;
    const int warp = tid >> 5;               // 0..15

    extern __shared__ unsigned char smem[];
    unsigned char* s_mask = smem;                         // n bytes
    unsigned long long* s_slot =
        (unsigned long long*)(smem + ((n + 7) & ~7));     // [2][16] packed
    int* s_far  = (int*)(s_slot + 32);
    int* s_qidx = s_far + 1;                              // m ints

    // Stage mask (needed only for the initial k-th-valid index).
    const int  mode  = mask_mode(mask);
    const long mbase = (long)b * n;
    for (int j = tid; j < n; j += nthr)
        s_mask[j] = mask_at(mask, mode, mbase + j) ? 1 : 0;
    __syncthreads();

    // Initial farthest = index of k-th True, k = rand_start[b] % count.
    if (tid < 32) {
        const int chunk = (n + 31) / 32;
        const int base  = lane * chunk;
        int cnt = 0;
        for (int i = 0; i < chunk; i++) {
            int jj = base + i;
            if (jj < n) cnt += s_mask[jj];
        }
        int inc = cnt;
        #pragma unroll
        for (int off = 1; off < 32; off <<= 1) {
            int v = __shfl_up_sync(FULL_MASK, inc, off);
            if (lane >= off) inc += v;
        }
        const int total = __shfl_sync(FULL_MASK, inc, 31);
        const int k     = rand_start[b] % total;
        const int excl  = inc - cnt;
        if (k >= excl && k < inc) {
            int need = k - excl;
            for (int i = 0; i < chunk; i++) {
                int jj = base + i;
                if (jj < n && s_mask[jj]) {
                    if (need == 0) { *s_far = jj; break; }
                    need--;
                }
            }
        }
    }
    __syncthreads();

    const int nq = n >> 2;                    // 512
    // far held as ELEMENT OFFSET (j * nq) throughout the loop.
    int far_off = (*s_far) * nq;

    // Encoded running distances (init enc(1e8)).
    const unsigned E_INIT = enc_f32(1e8f);
    uint4 dist = make_uint4(E_INIT, E_INIT, E_INIT, E_INIT);

    const uint4* dmb = (const uint4*)(g_dm) + (size_t)b * n * nq;

    for (int t = 0; t < m; t++) {
        // Row read: 8 KB from L2 (whole dm fits in L2 after precompute).
        uint4 v = __ldg(dmb + (size_t)far_off + tid);
        if (tid == 0) s_qidx[t] = far_off;    // STS: shared pipe, off-path

        dist.x = min(dist.x, v.x);
        dist.y = min(dist.y, v.y);
        dist.z = min(dist.z, v.z);
        dist.w = min(dist.w, v.w);

        // Local argmax over 4, tree-shaped (tie -> lowest j).
        unsigned kxy = (dist.y > dist.x) ? dist.y : dist.x;
        int      jxy = (dist.y > dist.x) ? 1 : 0;
        unsigned kzw = (dist.w > dist.z) ? dist.w : dist.z;
        int      jzw = (dist.w > dist.z) ? 3 : 2;
        unsigned bk  = (kzw > kxy) ? kzw : kxy;
        int      bj  = ((kzw > kxy) ? jzw : jxy) + (tid << 2);

        // Warp argmax: REDUX max on keys, REDUX min on selected SCALED
        // offset (ties -> lowest j; scaling by nq>0 preserves order).
        unsigned mk = __reduce_max_sync(FULL_MASK, bk);
        int      wo = __reduce_min_sync(FULL_MASK,
                                        (bk == mk) ? bj * nq : 0x7FFFFFFF);
        const int buf = (t & 1) << 4;
        if (lane == 0)
            s_slot[buf + warp] = ((unsigned long long)mk << 32) | (unsigned)wo;
        __syncthreads();

        // Redundant final reduce in EVERY warp (no second barrier needed:
        // next iter writes the other buffer, and its own barrier fences it).
        unsigned long long pk = (lane < 16) ? s_slot[buf + lane] : 0ull;
        unsigned k2 = (unsigned)(pk >> 32);              // 0 for lanes >= 16
        int      o2 = (int)(unsigned)pk;
        unsigned mk2 = __reduce_max_sync(FULL_MASK, k2); // keys never 0
        far_off      = __reduce_min_sync(FULL_MASK,
                                         (k2 == mk2) ? o2 : 0x7FFFFFFF);
    }

    // Bulk-write chosen indices (decode element offset -> j).
    __syncthreads();
    for (int t = tid; t < m; t += nthr)
        g_qidx[b * m + t] = s_qidx[t] / nq;
}

// ---------------------------------------------------------------------------
// Merged gathers: pairs (sub_abq float4 + sub_edges float2) then small
// (sub_vals float4 chunks + sub_mask) in one launch.
// ---------------------------------------------------------------------------
__global__ void gather_kernel(const float4* __restrict__ abq,
                              const float2* __restrict__ edges,
                              const float4* __restrict__ vals4,
                              const void* __restrict__ mask,
                              float4* __restrict__ out_abq,
                              float2* __restrict__ out_edges,
                              float4* __restrict__ out_vals,
                              float* __restrict__ out_mask,
                              int n, int m, int bs, int c4) {
    int idx = blockIdx.x * blockDim.x + threadIdx.x;
    int total_pairs = bs * m * m;
    if (idx < total_pairs) {
        int j = idx % m;
        int r = idx / m;
        int i = r % m;
        int b = r / m;
        int qi = g_qidx[b * m + i];
        int qj = g_qidx[b * m + j];
        size_t src = ((size_t)b * n + (size_t)qi) * (size_t)n + (size_t)qj;
        out_abq[idx]   = __ldg(abq + src);
        out_edges[idx] = __ldg(edges + src);
    } else {
        int k = idx - total_pairs;
        if (k >= bs * m * c4) return;
        int ch = k % c4;
        int r  = k / c4;
        int i  = r % m;
        int b  = r / m;
        int qi = g_qidx[b * m + i];
        out_vals[k] = __ldg(vals4 + ((size_t)b * n + (size_t)qi) * (size_t)c4 + ch);
        if (ch == 0) {
            int mode = mask_mode(mask);
            out_mask[b * m + i] = mask_at(mask, mode, (long)b * n + qi) ? 1.0f : 0.0f;
        }
    }
}

// ---------------------------------------------------------------------------
// Launch. Inputs: abq_pairs f32 (bs,n,n,4), vals f32 (bs,n,64), mask bool
// (bs,n), edges f32 (bs,n,n,2), rand_start i32 (bs).
// Output: [sub_abq | sub_vals | sub_mask | sub_edges] as f32.
// ---------------------------------------------------------------------------
extern "C" void kernel_launch(void* const* d_in, const int* in_sizes, int n_in,
                              void* d_out, int out_size) {
    const float4* abq   = (const float4*)d_in[0];
    const float4* vals4 = (const float4*)d_in[1];
    const void*   mask  = (const void*)d_in[2];
    const float2* edges = (const float2*)d_in[3];
    const int*    rnd   = (const int*)d_in[4];

    const int bs = in_sizes[4];                 // 4
    const int n  = in_sizes[2] / bs;            // 2048
    const int m  = n / 4;                       // 512
    const int c  = in_sizes[1] / (bs * n);      // 64
    const int c4 = c / 4;

    float* out = (float*)d_out;
    float4* out_abq    = (float4*)out;
    float*  out_vals_f = out + (size_t)bs * m * m * 4;
    float*  out_mask   = out_vals_f + (size_t)bs * m * c;
    float2* out_edges  = (float2*)(out_mask + (size_t)bs * m);

    // 1) Precompute encoded masked-distance matrix (R6-exact, ~51us).
    int total4 = bs * n * (n / 4);
    precompute_kernel<<<(total4 + 255) / 256, 256>>>(abq, mask, n, total4);

    // 2) Sequential FPS on the L2-resident encoded matrix.
    size_t smem = (size_t)((n + 7) & ~7) + 32 * sizeof(unsigned long long)
                + sizeof(int) + (size_t)m * sizeof(int);
    fps_kernel<<<bs, 512, smem>>>(mask, rnd, n, m);

    // 3) Merged output gathers.
    int total = bs * m * m + bs * m * c4;
    gather_kernel<<<(total + 255) / 256, 256>>>(
        abq, edges, vals4, mask,
        out_abq, out_edges, (float4*)out_vals_f, out_mask, n, m, bs, c4);
}